// round 5
// baseline (speedup 1.0000x reference)
#include <cuda_runtime.h>

// ---------------------------------------------------------------------------
// LocalAttentionND: x(2,64,64,256) -> qkv GEMM -> rmsnorm+rope -> 7x7 local
// soft-masked attention -> rmsnorm -> gate merge -> out GEMM.
// Round 4: GEMMs rebuilt on packed fma.rn.f32x2 (FFMA2): 128x128 tile, 8x8
// microtile, row-pair accumulators, B duplicated in smem so both FFMA2
// operands load as native 64-bit pairs (no packing instructions).
// ---------------------------------------------------------------------------

static constexpr int NTOK = 8192;      // 2*64*64
static constexpr int CDIM = 256;
static constexpr int QKVN = 768;

__device__ float g_qkv[NTOK * QKVN];     // silu(x@W_qkv); q/k rewritten in-place
__device__ float g_wp[NTOK * 8];         // width[4], sharp[4] per token
__device__ float g_outn[NTOK * CDIM];    // rmsnorm(attention out)
__device__ float g_merged[NTOK * CDIM];  // gate*v + (1-gate)*outn

__device__ __forceinline__ float fsig(float x)  { return 1.f / (1.f + __expf(-x)); }
__device__ __forceinline__ float fsilu(float x) { return x   / (1.f + __expf(-x)); }

__device__ __forceinline__ void ffma2(unsigned long long& acc,
                                      unsigned long long a,
                                      unsigned long long b)
{
    asm("fma.rn.f32x2 %0, %1, %2, %0;" : "+l"(acc) : "l"(a), "l"(b));
}

// ---------------------------------------------------------------------------
// GEMM: Cout = epi(A[M,256] @ W[256,N] (+bias)). Tile 128x128x16, 256 thr,
// 8x8 microtile on FFMA2 (row-pair packed accumulators).
// EPI=0: silu. EPI=1: gate-merge (A is v, outn blended in).
// ---------------------------------------------------------------------------
template <int EPI>
__global__ void __launch_bounds__(256, 2) gemm_k256(
    const float* __restrict__ A, int lda,
    const float* __restrict__ W, int ldw,
    const float* __restrict__ bias,
    float* __restrict__ Cout, int ldc,
    const float* __restrict__ outn)
{
    __shared__ __align__(16) float As[16][132];   // [k][m], 528B rows (16B mult)
    __shared__ __align__(16) float Bsd[16][260];  // [k][2n] duplicated pairs

    const int tid = threadIdx.x;
    const int tx = tid & 15;       // col group: cols tx*8 .. tx*8+7
    const int ty = tid >> 4;       // row group: rows ty*8 .. ty*8+7
    const int row0 = blockIdx.x * 128;
    const int col0 = blockIdx.y * 128;

    const int arow = tid >> 1;           // 0..127
    const int acol = (tid & 1) * 8;      // 0 or 8
    const int brow = tid >> 4;           // 0..15
    const int bcol = (tid & 15) * 8;     // 0..120

    const float* Ap = A + (size_t)(row0 + arow) * lda + acol;
    const float* Wp = W + (size_t)brow * ldw + col0 + bcol;

    unsigned long long acc[4][8];        // [row-pair][col], packed f32x2
#pragma unroll
    for (int i = 0; i < 4; i++)
#pragma unroll
        for (int j = 0; j < 8; j++) acc[i][j] = 0ull;

    // prologue: load first slab
    float4 na0 = *(const float4*)(Ap);
    float4 na1 = *(const float4*)(Ap + 4);
    float4 nb0 = *(const float4*)(Wp);
    float4 nb1 = *(const float4*)(Wp + 4);

    for (int k0 = 0; k0 < 256; k0 += 16) {
        As[acol + 0][arow] = na0.x; As[acol + 1][arow] = na0.y;
        As[acol + 2][arow] = na0.z; As[acol + 3][arow] = na0.w;
        As[acol + 4][arow] = na1.x; As[acol + 5][arow] = na1.y;
        As[acol + 6][arow] = na1.z; As[acol + 7][arow] = na1.w;
        {   // duplicated B pairs: (w,w) per value
            float* bd = &Bsd[brow][bcol * 2];
            ((float4*)bd)[0] = make_float4(nb0.x, nb0.x, nb0.y, nb0.y);
            ((float4*)bd)[1] = make_float4(nb0.z, nb0.z, nb0.w, nb0.w);
            ((float4*)bd)[2] = make_float4(nb1.x, nb1.x, nb1.y, nb1.y);
            ((float4*)bd)[3] = make_float4(nb1.z, nb1.z, nb1.w, nb1.w);
        }
        __syncthreads();

        if (k0 + 16 < 256) {   // prefetch next slab; overlaps MMA below
            na0 = *(const float4*)(Ap + k0 + 16);
            na1 = *(const float4*)(Ap + k0 + 20);
            nb0 = *(const float4*)(Wp + (size_t)(k0 + 16) * ldw);
            nb1 = *(const float4*)(Wp + (size_t)(k0 + 16) * ldw + 4);
        }

#pragma unroll
        for (int kk = 0; kk < 16; kk++) {
            // a: 4 row-pairs as native 64-bit lanes
            ulonglong2 ap0 = *(const ulonglong2*)&As[kk][ty * 8];
            ulonglong2 ap1 = *(const ulonglong2*)&As[kk][ty * 8 + 4];
            unsigned long long ap[4] = {ap0.x, ap0.y, ap1.x, ap1.y};
            // b: 8 duplicated col-pairs
            const float* bd = &Bsd[kk][tx * 16];
            ulonglong2 bp0 = ((const ulonglong2*)bd)[0];
            ulonglong2 bp1 = ((const ulonglong2*)bd)[1];
            ulonglong2 bp2 = ((const ulonglong2*)bd)[2];
            ulonglong2 bp3 = ((const ulonglong2*)bd)[3];
            unsigned long long bp[8] = {bp0.x, bp0.y, bp1.x, bp1.y,
                                        bp2.x, bp2.y, bp3.x, bp3.y};
#pragma unroll
            for (int i = 0; i < 4; i++)
#pragma unroll
                for (int j = 0; j < 8; j++)
                    ffma2(acc[i][j], ap[i], bp[j]);
        }
        __syncthreads();
    }

    // epilogue: unpack row pairs
#pragma unroll
    for (int i = 0; i < 4; i++) {
#pragma unroll
        for (int half = 0; half < 2; half++) {
            int row = row0 + ty * 8 + i * 2 + half;
            float c[8];
#pragma unroll
            for (int j = 0; j < 8; j++) {
                float2 p = *(const float2*)&acc[i][j];
                c[j] = half ? p.y : p.x;
            }
            int col = col0 + tx * 8;
            if (EPI == 0) {
                float4 r0, r1;
                r0.x = fsilu(c[0]); r0.y = fsilu(c[1]);
                r0.z = fsilu(c[2]); r0.w = fsilu(c[3]);
                r1.x = fsilu(c[4]); r1.y = fsilu(c[5]);
                r1.z = fsilu(c[6]); r1.w = fsilu(c[7]);
                *(float4*)(Cout + (size_t)row * ldc + col)     = r0;
                *(float4*)(Cout + (size_t)row * ldc + col + 4) = r1;
            } else {
#pragma unroll
                for (int q = 0; q < 2; q++) {
                    float4 v4 = *(const float4*)(A + (size_t)row * lda + col + q * 4);
                    float4 o4 = *(const float4*)(outn + (size_t)row * CDIM + col + q * 4);
                    float4 b4 = *(const float4*)(bias + col + q * 4);
                    float4 r;
                    float g;
                    g = fsig(fsilu(c[q*4+0] + b4.x)); r.x = g * v4.x + (1.f - g) * o4.x;
                    g = fsig(fsilu(c[q*4+1] + b4.y)); r.y = g * v4.y + (1.f - g) * o4.y;
                    g = fsig(fsilu(c[q*4+2] + b4.z)); r.z = g * v4.z + (1.f - g) * o4.z;
                    g = fsig(fsilu(c[q*4+3] + b4.w)); r.w = g * v4.w + (1.f - g) * o4.w;
                    *(float4*)(Cout + (size_t)row * ldc + col + q * 4) = r;
                }
            }
        }
    }
}

// ---------------------------------------------------------------------------
// wp = silu(x @ W_wp + b_wp); width = sig(.)*maxd+0.5, sharp = sig(.)*9.5+0.5
// ---------------------------------------------------------------------------
__global__ void __launch_bounds__(256) wp_kernel(
    const float* __restrict__ x, const float* __restrict__ W_wp,
    const float* __restrict__ b_wp, float* __restrict__ wp_out)
{
    int warp = (blockIdx.x * blockDim.x + threadIdx.x) >> 5;
    int lane = threadIdx.x & 31;
    if (warp >= NTOK) return;
    const float* xr = x + (size_t)warp * CDIM;
    float acc[8] = {};
    for (int k = lane; k < CDIM; k += 32) {
        float xv = xr[k];
        const float* wr = W_wp + k * 8;
#pragma unroll
        for (int o = 0; o < 8; o++) acc[o] += xv * wr[o];
    }
#pragma unroll
    for (int o = 0; o < 8; o++)
#pragma unroll
        for (int off = 16; off; off >>= 1)
            acc[o] += __shfl_xor_sync(0xffffffffu, acc[o], off);
    if (lane < 8) {
        const float maxd = 4.242640687119285f;  // sqrt(18)
        float t = acc[lane] + b_wp[lane];
        float s = fsilu(t);
        float sg = fsig(s);
        wp_out[warp * 8 + lane] = (lane < 4) ? (sg * maxd + 0.5f) : (sg * 9.5f + 0.5f);
    }
}

// ---------------------------------------------------------------------------
// In-place rmsnorm (per head, D=64) + RoPE (position = head index) on q, k.
// ---------------------------------------------------------------------------
__global__ void __launch_bounds__(256) rmsrope_kernel(
    const float* __restrict__ w_qnorm, const float* __restrict__ w_knorm)
{
    int token = blockIdx.x;
    int warpId = threadIdx.x >> 5, lane = threadIdx.x & 31;
    int which = warpId >> 2;    // 0=q, 1=k
    int head  = warpId & 3;
    const float* wn = which ? w_knorm : w_qnorm;
    float* base = g_qkv + (size_t)token * QKVN + which * CDIM + head * 64;

    float x1 = base[lane], x2 = base[lane + 32];
    float ss = x1 * x1 + x2 * x2;
#pragma unroll
    for (int off = 16; off; off >>= 1) ss += __shfl_xor_sync(0xffffffffu, ss, off);
    float inv = rsqrtf(ss * (1.f / 64.f) + 1e-6f);
    x1 = x1 * inv * wn[lane];
    x2 = x2 * inv * wn[lane + 32];

    float freq = exp2f(-(float)lane * (13.287712379549449f / 32.f));  // log2(10000)/32
    float ang = (float)head * freq;
    float c = cosf(ang), s = sinf(ang);
    base[lane]      = x1 * c - x2 * s;
    base[lane + 32] = x1 * s + x2 * c;
}

// ---------------------------------------------------------------------------
// Attention: 1 warp per (token, head), 2 tokens per 256-thread block.
// Phase 1: 4 groups of 8 lanes; group = window, lane = 8 channels (coalesced).
// Phase 2: warp softmax (scores via smem).
// Phase 3: lane = channel, coalesced v gathers. Fused per-token rmsnorm.
// ---------------------------------------------------------------------------
__global__ void __launch_bounds__(256) attn_kernel(const float* __restrict__ w_onorm)
{
    __shared__ __align__(16) float s_q[8][64];
    __shared__ float s_p[8][52];
    __shared__ float s_out[2][256];
    __shared__ float s_ss[2];

    const int warpId = threadIdx.x >> 5, lane = threadIdx.x & 31;
    const int tl = warpId >> 2;      // token-local 0/1
    const int head = warpId & 3;
    const int token = blockIdx.x * 2 + tl;
    const int b = token >> 12;
    const int yx = token & 4095;
    const int y = yx >> 6, xx = yx & 63;

    if (threadIdx.x < 2) s_ss[threadIdx.x] = 0.f;

    const float* qrow = g_qkv + (size_t)token * QKVN + head * 64;
    s_q[warpId][lane]      = qrow[lane];
    s_q[warpId][lane + 32] = qrow[lane + 32];
    __syncwarp();

    const int sub = lane & 7;        // lane within group
    const int grp = lane >> 3;       // group = window within round
    float4 q4a = ((const float4*)s_q[warpId])[sub];
    float4 q4b = ((const float4*)s_q[warpId])[sub + 8];

    const float width = g_wp[token * 8 + head];
    const float sharp = g_wp[token * 8 + 4 + head];
    const float* kbase = g_qkv + 256 + (size_t)head * 64;

#pragma unroll
    for (int r = 0; r < 13; r++) {
        int w = r * 4 + grp;
        bool act = (w < 49);
        int wc = act ? w : 48;
        int di = wc / 7 - 3, dj = wc % 7 - 3;
        int ny = y + di, nx = xx + dj;
        float part = 0.f;
        if (act & ((unsigned)ny < 64u) & ((unsigned)nx < 64u)) {
            const float4* kr = (const float4*)(kbase +
                (size_t)((b << 12) + (ny << 6) + nx) * QKVN);
            float4 ka = kr[sub];
            float4 kb = kr[sub + 8];
            part = q4a.x * ka.x + q4a.y * ka.y + q4a.z * ka.z + q4a.w * ka.w
                 + q4b.x * kb.x + q4b.y * kb.y + q4b.z * kb.z + q4b.w * kb.w;
        }
        part += __shfl_xor_sync(0xffffffffu, part, 1);
        part += __shfl_xor_sync(0xffffffffu, part, 2);
        part += __shfl_xor_sync(0xffffffffu, part, 4);
        if (act && sub == 0) {
            float rd = sqrtf((float)(di * di + dj * dj));
            float mask = fsig((width - rd) * sharp);
            s_p[warpId][w] = part * 0.125f - (1.f - mask) * 10000.f;
        }
    }
    __syncwarp();

    float sc0 = s_p[warpId][lane];
    float sc1 = (lane + 32 < 49) ? s_p[warpId][lane + 32] : -1e30f;
    float mx = fmaxf(sc0, sc1);
#pragma unroll
    for (int off = 16; off; off >>= 1) mx = fmaxf(mx, __shfl_xor_sync(0xffffffffu, mx, off));
    float p0 = __expf(sc0 - mx);
    float p1 = __expf(sc1 - mx);
    float ds = p0 + p1;
#pragma unroll
    for (int off = 16; off; off >>= 1) ds += __shfl_xor_sync(0xffffffffu, ds, off);
    float rdm = 1.f / ds;
    s_p[warpId][lane] = p0 * rdm;
    if (lane + 32 < 49) s_p[warpId][lane + 32] = p1 * rdm;
    __syncwarp();

    float o0 = 0.f, o1 = 0.f;
#pragma unroll
    for (int ii = 0; ii < 7; ii++) {
        int ny = y + ii - 3;
        if ((unsigned)ny >= 64u) continue;
        const float* rowbase = g_qkv + (size_t)((b << 12) + (ny << 6)) * QKVN
                             + 512 + head * 64;
#pragma unroll
        for (int jj = 0; jj < 7; jj++) {
            int nx = xx + jj - 3;
            if ((unsigned)nx >= 64u) continue;
            float p = s_p[warpId][ii * 7 + jj];
            const float* vrow = rowbase + (size_t)nx * QKVN;
            o0 += p * vrow[lane];
            o1 += p * vrow[lane + 32];
        }
    }

    s_out[tl][head * 64 + lane]      = o0;
    s_out[tl][head * 64 + lane + 32] = o1;

    float pss = o0 * o0 + o1 * o1;
#pragma unroll
    for (int off = 16; off; off >>= 1) pss += __shfl_xor_sync(0xffffffffu, pss, off);
    __syncthreads();            // s_ss init + s_out visible
    if (lane == 0) atomicAdd(&s_ss[tl], pss);
    __syncthreads();

    for (int e = threadIdx.x; e < 512; e += 256) {
        int t2 = e >> 8, c = e & 255;
        float rinv = rsqrtf(s_ss[t2] * (1.f / 256.f) + 1e-6f);
        g_outn[(size_t)(blockIdx.x * 2 + t2) * CDIM + c] = s_out[t2][c] * rinv * w_onorm[c];
    }
}

// ---------------------------------------------------------------------------
extern "C" void kernel_launch(void* const* d_in, const int* in_sizes, int n_in,
                              void* d_out, int out_size)
{
    const float* x       = (const float*)d_in[0];
    const float* W_qkv   = (const float*)d_in[1];
    const float* w_qnorm = (const float*)d_in[2];
    const float* w_knorm = (const float*)d_in[3];
    const float* W_wp    = (const float*)d_in[4];
    const float* b_wp    = (const float*)d_in[5];
    const float* w_onorm = (const float*)d_in[6];
    const float* W_out   = (const float*)d_in[7];
    const float* W_gate  = (const float*)d_in[8];
    const float* b_gate  = (const float*)d_in[9];
    float* out = (float*)d_out;

    float *p_qkv, *p_wp, *p_outn, *p_merged;
    cudaGetSymbolAddress((void**)&p_qkv, g_qkv);
    cudaGetSymbolAddress((void**)&p_wp, g_wp);
    cudaGetSymbolAddress((void**)&p_outn, g_outn);
    cudaGetSymbolAddress((void**)&p_merged, g_merged);

    // 1. qkv = silu(x @ W_qkv)
    gemm_k256<0><<<dim3(NTOK / 128, QKVN / 128), 256>>>(x, CDIM, W_qkv, QKVN, nullptr,
                                                        p_qkv, QKVN, nullptr);
    // 2. width/sharpness projection
    wp_kernel<<<NTOK / 8, 256>>>(x, W_wp, b_wp, p_wp);
    // 3. rmsnorm + rope on q, k (in place)
    rmsrope_kernel<<<NTOK, 256>>>(w_qnorm, w_knorm);
    // 4. windowed attention + fused output rmsnorm
    attn_kernel<<<NTOK / 2, 256>>>(w_onorm);
    // 5. gate GEMM + merge epilogue: merged = gate*v + (1-gate)*outn
    gemm_k256<1><<<dim3(NTOK / 128, CDIM / 128), 256>>>(p_qkv + 512, QKVN, W_gate, CDIM,
                                                        b_gate, p_merged, CDIM, p_outn);
    // 6. final: silu(merged @ W_out)
    gemm_k256<0><<<dim3(NTOK / 128, CDIM / 128), 256>>>(p_merged, CDIM, W_out, CDIM, nullptr,
                                                        out, CDIM, nullptr);
}

// round 7
// speedup vs baseline: 2.1241x; 2.1241x over previous
#include <cuda_runtime.h>

// ---------------------------------------------------------------------------
// LocalAttentionND: x(2,64,64,256) -> qkv GEMM -> rmsnorm+rope -> 7x7 local
// soft-masked attention -> rmsnorm -> gate merge -> out GEMM.
// Round 6: REVERT GEMM to round-4 form (FFMA2 experiment regressed: smem bank
// conflicts + no true FFMA2 emission). Keep round-5 attention (64.7us).
// ---------------------------------------------------------------------------

static constexpr int NTOK = 8192;      // 2*64*64
static constexpr int CDIM = 256;
static constexpr int QKVN = 768;

__device__ float g_qkv[NTOK * QKVN];     // silu(x@W_qkv); q/k rewritten in-place
__device__ float g_wp[NTOK * 8];         // width[4], sharp[4] per token
__device__ float g_outn[NTOK * CDIM];    // rmsnorm(attention out)
__device__ float g_merged[NTOK * CDIM];  // gate*v + (1-gate)*outn

__device__ __forceinline__ float fsig(float x)  { return 1.f / (1.f + __expf(-x)); }
__device__ __forceinline__ float fsilu(float x) { return x   / (1.f + __expf(-x)); }

// ---------------------------------------------------------------------------
// GEMM: Cout = epi(A[M,256] @ W[256,N] (+bias)). Tile 128x64x16, 256 thr,
// 8x4 microtile, register-prefetch pipelined global->smem staging.
// EPI=0: silu. EPI=1: gate-merge (A is v, outn blended in).
// ---------------------------------------------------------------------------
template <int EPI>
__global__ void __launch_bounds__(256) gemm_k256(
    const float* __restrict__ A, int lda,
    const float* __restrict__ W, int ldw,
    const float* __restrict__ bias,
    float* __restrict__ Cout, int ldc,
    const float* __restrict__ outn)
{
    __shared__ __align__(16) float As[16][132];  // [k][m]
    __shared__ __align__(16) float Bs[16][64];   // [k][n]

    const int tid = threadIdx.x;
    const int tx = tid & 15;
    const int ty = tid >> 4;
    const int row0 = blockIdx.x * 128;
    const int col0 = blockIdx.y * 64;

    const int arow = tid >> 1;           // 0..127
    const int acol = (tid & 1) * 8;      // 0 or 8
    const int brow = tid >> 4;           // 0..15
    const int bcol = (tid & 15) * 4;     // 0..60

    const float* Ap = A + (size_t)(row0 + arow) * lda + acol;
    const float* Wp = W + (size_t)brow * ldw + col0 + bcol;

    float acc[8][4] = {};

    // prologue: load first slab
    float4 na0 = *(const float4*)(Ap);
    float4 na1 = *(const float4*)(Ap + 4);
    float4 nb  = *(const float4*)(Wp);

    for (int k0 = 0; k0 < 256; k0 += 16) {
        As[acol + 0][arow] = na0.x; As[acol + 1][arow] = na0.y;
        As[acol + 2][arow] = na0.z; As[acol + 3][arow] = na0.w;
        As[acol + 4][arow] = na1.x; As[acol + 5][arow] = na1.y;
        As[acol + 6][arow] = na1.z; As[acol + 7][arow] = na1.w;
        *(float4*)&Bs[brow][bcol] = nb;
        __syncthreads();

        if (k0 + 16 < 256) {   // prefetch next slab; overlaps MMA below
            na0 = *(const float4*)(Ap + k0 + 16);
            na1 = *(const float4*)(Ap + k0 + 20);
            nb  = *(const float4*)(Wp + (size_t)(k0 + 16) * ldw);
        }

#pragma unroll
        for (int kk = 0; kk < 16; kk++) {
            float4 b  = *(const float4*)&Bs[kk][tx * 4];
            float4 x0 = *(const float4*)&As[kk][ty * 8];
            float4 x1 = *(const float4*)&As[kk][ty * 8 + 4];
            float av[8] = {x0.x, x0.y, x0.z, x0.w, x1.x, x1.y, x1.z, x1.w};
#pragma unroll
            for (int i = 0; i < 8; i++) {
                acc[i][0] += av[i] * b.x;
                acc[i][1] += av[i] * b.y;
                acc[i][2] += av[i] * b.z;
                acc[i][3] += av[i] * b.w;
            }
        }
        __syncthreads();
    }

#pragma unroll
    for (int i = 0; i < 8; i++) {
        int row = row0 + ty * 8 + i;
        int col = col0 + tx * 4;
        float4 r;
        if (EPI == 0) {
            r.x = fsilu(acc[i][0]);
            r.y = fsilu(acc[i][1]);
            r.z = fsilu(acc[i][2]);
            r.w = fsilu(acc[i][3]);
        } else {
            float4 v4 = *(const float4*)(A + (size_t)row * lda + col);
            float4 o4 = *(const float4*)(outn + (size_t)row * CDIM + col);
            float4 b4 = *(const float4*)(bias + col);
            float g;
            g = fsig(fsilu(acc[i][0] + b4.x)); r.x = g * v4.x + (1.f - g) * o4.x;
            g = fsig(fsilu(acc[i][1] + b4.y)); r.y = g * v4.y + (1.f - g) * o4.y;
            g = fsig(fsilu(acc[i][2] + b4.z)); r.z = g * v4.z + (1.f - g) * o4.z;
            g = fsig(fsilu(acc[i][3] + b4.w)); r.w = g * v4.w + (1.f - g) * o4.w;
        }
        *(float4*)(Cout + (size_t)row * ldc + col) = r;
    }
}

// ---------------------------------------------------------------------------
// wp = silu(x @ W_wp + b_wp); width = sig(.)*maxd+0.5, sharp = sig(.)*9.5+0.5
// ---------------------------------------------------------------------------
__global__ void __launch_bounds__(256) wp_kernel(
    const float* __restrict__ x, const float* __restrict__ W_wp,
    const float* __restrict__ b_wp, float* __restrict__ wp_out)
{
    int warp = (blockIdx.x * blockDim.x + threadIdx.x) >> 5;
    int lane = threadIdx.x & 31;
    if (warp >= NTOK) return;
    const float* xr = x + (size_t)warp * CDIM;
    float acc[8] = {};
    for (int k = lane; k < CDIM; k += 32) {
        float xv = xr[k];
        const float* wr = W_wp + k * 8;
#pragma unroll
        for (int o = 0; o < 8; o++) acc[o] += xv * wr[o];
    }
#pragma unroll
    for (int o = 0; o < 8; o++)
#pragma unroll
        for (int off = 16; off; off >>= 1)
            acc[o] += __shfl_xor_sync(0xffffffffu, acc[o], off);
    if (lane < 8) {
        const float maxd = 4.242640687119285f;  // sqrt(18)
        float t = acc[lane] + b_wp[lane];
        float s = fsilu(t);
        float sg = fsig(s);
        wp_out[warp * 8 + lane] = (lane < 4) ? (sg * maxd + 0.5f) : (sg * 9.5f + 0.5f);
    }
}

// ---------------------------------------------------------------------------
// In-place rmsnorm (per head, D=64) + RoPE (position = head index) on q, k.
// ---------------------------------------------------------------------------
__global__ void __launch_bounds__(256) rmsrope_kernel(
    const float* __restrict__ w_qnorm, const float* __restrict__ w_knorm)
{
    int token = blockIdx.x;
    int warpId = threadIdx.x >> 5, lane = threadIdx.x & 31;
    int which = warpId >> 2;    // 0=q, 1=k
    int head  = warpId & 3;
    const float* wn = which ? w_knorm : w_qnorm;
    float* base = g_qkv + (size_t)token * QKVN + which * CDIM + head * 64;

    float x1 = base[lane], x2 = base[lane + 32];
    float ss = x1 * x1 + x2 * x2;
#pragma unroll
    for (int off = 16; off; off >>= 1) ss += __shfl_xor_sync(0xffffffffu, ss, off);
    float inv = rsqrtf(ss * (1.f / 64.f) + 1e-6f);
    x1 = x1 * inv * wn[lane];
    x2 = x2 * inv * wn[lane + 32];

    float freq = exp2f(-(float)lane * (13.287712379549449f / 32.f));  // log2(10000)/32
    float ang = (float)head * freq;
    float c = cosf(ang), s = sinf(ang);
    base[lane]      = x1 * c - x2 * s;
    base[lane + 32] = x1 * s + x2 * c;
}

// ---------------------------------------------------------------------------
// Attention: 1 warp per (token, head), 2 tokens per 256-thread block.
// Phase 1: 4 groups of 8 lanes; group = window, lane = 8 channels (coalesced).
// Phase 2: warp softmax (scores via smem).
// Phase 3: lane = channel, coalesced v gathers. Fused per-token rmsnorm.
// ---------------------------------------------------------------------------
__global__ void __launch_bounds__(256) attn_kernel(const float* __restrict__ w_onorm)
{
    __shared__ __align__(16) float s_q[8][64];
    __shared__ float s_p[8][52];
    __shared__ float s_out[2][256];
    __shared__ float s_ss[2];

    const int warpId = threadIdx.x >> 5, lane = threadIdx.x & 31;
    const int tl = warpId >> 2;      // token-local 0/1
    const int head = warpId & 3;
    const int token = blockIdx.x * 2 + tl;
    const int b = token >> 12;
    const int yx = token & 4095;
    const int y = yx >> 6, xx = yx & 63;

    if (threadIdx.x < 2) s_ss[threadIdx.x] = 0.f;

    const float* qrow = g_qkv + (size_t)token * QKVN + head * 64;
    s_q[warpId][lane]      = qrow[lane];
    s_q[warpId][lane + 32] = qrow[lane + 32];
    __syncwarp();

    const int sub = lane & 7;        // lane within group
    const int grp = lane >> 3;       // group = window within round
    float4 q4a = ((const float4*)s_q[warpId])[sub];
    float4 q4b = ((const float4*)s_q[warpId])[sub + 8];

    const float width = g_wp[token * 8 + head];
    const float sharp = g_wp[token * 8 + 4 + head];
    const float* kbase = g_qkv + 256 + (size_t)head * 64;

#pragma unroll
    for (int r = 0; r < 13; r++) {
        int w = r * 4 + grp;
        bool act = (w < 49);
        int wc = act ? w : 48;
        int di = wc / 7 - 3, dj = wc % 7 - 3;
        int ny = y + di, nx = xx + dj;
        float part = 0.f;
        if (act & ((unsigned)ny < 64u) & ((unsigned)nx < 64u)) {
            const float4* kr = (const float4*)(kbase +
                (size_t)((b << 12) + (ny << 6) + nx) * QKVN);
            float4 ka = kr[sub];
            float4 kb = kr[sub + 8];
            part = q4a.x * ka.x + q4a.y * ka.y + q4a.z * ka.z + q4a.w * ka.w
                 + q4b.x * kb.x + q4b.y * kb.y + q4b.z * kb.z + q4b.w * kb.w;
        }
        part += __shfl_xor_sync(0xffffffffu, part, 1);
        part += __shfl_xor_sync(0xffffffffu, part, 2);
        part += __shfl_xor_sync(0xffffffffu, part, 4);
        if (act && sub == 0) {
            float rd = sqrtf((float)(di * di + dj * dj));
            float mask = fsig((width - rd) * sharp);
            s_p[warpId][w] = part * 0.125f - (1.f - mask) * 10000.f;
        }
    }
    __syncwarp();

    float sc0 = s_p[warpId][lane];
    float sc1 = (lane + 32 < 49) ? s_p[warpId][lane + 32] : -1e30f;
    float mx = fmaxf(sc0, sc1);
#pragma unroll
    for (int off = 16; off; off >>= 1) mx = fmaxf(mx, __shfl_xor_sync(0xffffffffu, mx, off));
    float p0 = __expf(sc0 - mx);
    float p1 = __expf(sc1 - mx);
    float ds = p0 + p1;
#pragma unroll
    for (int off = 16; off; off >>= 1) ds += __shfl_xor_sync(0xffffffffu, ds, off);
    float rdm = 1.f / ds;
    s_p[warpId][lane] = p0 * rdm;
    if (lane + 32 < 49) s_p[warpId][lane + 32] = p1 * rdm;
    __syncwarp();

    float o0 = 0.f, o1 = 0.f;
#pragma unroll
    for (int ii = 0; ii < 7; ii++) {
        int ny = y + ii - 3;
        if ((unsigned)ny >= 64u) continue;
        const float* rowbase = g_qkv + (size_t)((b << 12) + (ny << 6)) * QKVN
                             + 512 + head * 64;
#pragma unroll
        for (int jj = 0; jj < 7; jj++) {
            int nx = xx + jj - 3;
            if ((unsigned)nx >= 64u) continue;
            float p = s_p[warpId][ii * 7 + jj];
            const float* vrow = rowbase + (size_t)nx * QKVN;
            o0 += p * vrow[lane];
            o1 += p * vrow[lane + 32];
        }
    }

    s_out[tl][head * 64 + lane]      = o0;
    s_out[tl][head * 64 + lane + 32] = o1;

    float pss = o0 * o0 + o1 * o1;
#pragma unroll
    for (int off = 16; off; off >>= 1) pss += __shfl_xor_sync(0xffffffffu, pss, off);
    __syncthreads();            // s_ss init + s_out visible
    if (lane == 0) atomicAdd(&s_ss[tl], pss);
    __syncthreads();

    for (int e = threadIdx.x; e < 512; e += 256) {
        int t2 = e >> 8, c = e & 255;
        float rinv = rsqrtf(s_ss[t2] * (1.f / 256.f) + 1e-6f);
        g_outn[(size_t)(blockIdx.x * 2 + t2) * CDIM + c] = s_out[t2][c] * rinv * w_onorm[c];
    }
}

// ---------------------------------------------------------------------------
extern "C" void kernel_launch(void* const* d_in, const int* in_sizes, int n_in,
                              void* d_out, int out_size)
{
    const float* x       = (const float*)d_in[0];
    const float* W_qkv   = (const float*)d_in[1];
    const float* w_qnorm = (const float*)d_in[2];
    const float* w_knorm = (const float*)d_in[3];
    const float* W_wp    = (const float*)d_in[4];
    const float* b_wp    = (const float*)d_in[5];
    const float* w_onorm = (const float*)d_in[6];
    const float* W_out   = (const float*)d_in[7];
    const float* W_gate  = (const float*)d_in[8];
    const float* b_gate  = (const float*)d_in[9];
    float* out = (float*)d_out;

    float *p_qkv, *p_wp, *p_outn, *p_merged;
    cudaGetSymbolAddress((void**)&p_qkv, g_qkv);
    cudaGetSymbolAddress((void**)&p_wp, g_wp);
    cudaGetSymbolAddress((void**)&p_outn, g_outn);
    cudaGetSymbolAddress((void**)&p_merged, g_merged);

    // 1. qkv = silu(x @ W_qkv)
    gemm_k256<0><<<dim3(NTOK / 128, QKVN / 64), 256>>>(x, CDIM, W_qkv, QKVN, nullptr,
                                                       p_qkv, QKVN, nullptr);
    // 2. width/sharpness projection
    wp_kernel<<<NTOK / 8, 256>>>(x, W_wp, b_wp, p_wp);
    // 3. rmsnorm + rope on q, k (in place)
    rmsrope_kernel<<<NTOK, 256>>>(w_qnorm, w_knorm);
    // 4. windowed attention + fused output rmsnorm
    attn_kernel<<<NTOK / 2, 256>>>(w_onorm);
    // 5. gate GEMM + merge epilogue: merged = gate*v + (1-gate)*outn
    gemm_k256<1><<<dim3(NTOK / 128, CDIM / 64), 256>>>(p_qkv + 512, QKVN, W_gate, CDIM,
                                                       b_gate, p_merged, CDIM, p_outn);
    // 6. final: silu(merged @ W_out)
    gemm_k256<0><<<dim3(NTOK / 128, CDIM / 64), 256>>>(p_merged, CDIM, W_out, CDIM, nullptr,
                                                       out, CDIM, nullptr);
}

// round 8
// speedup vs baseline: 2.7389x; 1.2895x over previous
#include <cuda_runtime.h>
#include <cuda_bf16.h>
#include <cstdint>

// ---------------------------------------------------------------------------
// LocalAttentionND: x(2,64,64,256) -> qkv GEMM -> rmsnorm+rope -> 7x7 local
// soft-masked attention -> rmsnorm -> gate merge -> out GEMM.
// Round 7: GEMMs on tensor cores via bf16 split (hi/lo, 3-MMA compensated),
// mma.sync.m16n8k16 + ldmatrix. Attention unchanged (round-5 form).
// ---------------------------------------------------------------------------

static constexpr int NTOK = 8192;      // 2*64*64
static constexpr int CDIM = 256;
static constexpr int QKVN = 768;

__device__ float g_qkv[NTOK * QKVN];     // silu(x@W_qkv); q/k rewritten in-place
__device__ float g_wp[NTOK * 8];         // width[4], sharp[4] per token
__device__ float g_outn[NTOK * CDIM];    // rmsnorm(attention out)
__device__ float g_merged[NTOK * CDIM];  // gate*v + (1-gate)*outn

__device__ __forceinline__ float fsig(float x)  { return 1.f / (1.f + __expf(-x)); }
__device__ __forceinline__ float fsilu(float x) { return x   / (1.f + __expf(-x)); }

// ---------------------------------------------------------------------------
// tensor-core helpers
// ---------------------------------------------------------------------------
__device__ __forceinline__ void ldsm_x4(uint32_t addr, uint32_t& r0, uint32_t& r1,
                                        uint32_t& r2, uint32_t& r3)
{
    asm volatile("ldmatrix.sync.aligned.m8n8.x4.shared.b16 {%0,%1,%2,%3}, [%4];"
                 : "=r"(r0), "=r"(r1), "=r"(r2), "=r"(r3) : "r"(addr));
}
__device__ __forceinline__ void ldsm_x4_t(uint32_t addr, uint32_t& r0, uint32_t& r1,
                                          uint32_t& r2, uint32_t& r3)
{
    asm volatile("ldmatrix.sync.aligned.m8n8.x4.trans.shared.b16 {%0,%1,%2,%3}, [%4];"
                 : "=r"(r0), "=r"(r1), "=r"(r2), "=r"(r3) : "r"(addr));
}
__device__ __forceinline__ void mma16816(float* c, const uint32_t* a,
                                         uint32_t b0, uint32_t b1)
{
    asm volatile(
        "mma.sync.aligned.m16n8k16.row.col.f32.bf16.bf16.f32 "
        "{%0,%1,%2,%3}, {%4,%5,%6,%7}, {%8,%9}, {%0,%1,%2,%3};"
        : "+f"(c[0]), "+f"(c[1]), "+f"(c[2]), "+f"(c[3])
        : "r"(a[0]), "r"(a[1]), "r"(a[2]), "r"(a[3]), "r"(b0), "r"(b1));
}

// convert float4 -> 4 bf16 hi + 4 bf16 lo, store as 8B each
__device__ __forceinline__ void store_hilo(__nv_bfloat16* hp, __nv_bfloat16* lp, float4 v)
{
    __nv_bfloat16 h0 = __float2bfloat16_rn(v.x);
    __nv_bfloat16 h1 = __float2bfloat16_rn(v.y);
    __nv_bfloat16 h2 = __float2bfloat16_rn(v.z);
    __nv_bfloat16 h3 = __float2bfloat16_rn(v.w);
    __nv_bfloat162 hh0; hh0.x = h0; hh0.y = h1;
    __nv_bfloat162 hh1; hh1.x = h2; hh1.y = h3;
    *(__nv_bfloat162*)(hp)     = hh0;
    *(__nv_bfloat162*)(hp + 2) = hh1;
    __nv_bfloat162 ll0, ll1;
    ll0.x = __float2bfloat16_rn(v.x - __bfloat162float(h0));
    ll0.y = __float2bfloat16_rn(v.y - __bfloat162float(h1));
    ll1.x = __float2bfloat16_rn(v.z - __bfloat162float(h2));
    ll1.y = __float2bfloat16_rn(v.w - __bfloat162float(h3));
    *(__nv_bfloat162*)(lp)     = ll0;
    *(__nv_bfloat162*)(lp + 2) = ll1;
}

// ---------------------------------------------------------------------------
// GEMM: Cout = epi(A[M,256] @ W[256,N] (+bias)). Tile 128x128x32, 256 thr,
// 8 warps (2x4), warp tile 64x32, bf16-split 3-MMA. K must be 256.
// EPI=0: silu. EPI=1: gate-merge (A is v, outn blended in).
// ---------------------------------------------------------------------------
template <int EPI>
__global__ void __launch_bounds__(256) gemm_bf16s(
    const float* __restrict__ A, int lda,
    const float* __restrict__ W, int ldw,
    const float* __restrict__ bias,
    float* __restrict__ Cout, int ldc,
    const float* __restrict__ outn)
{
    // A: [m][k] (k contiguous), rows padded to 40 bf16 (80B: 8 distinct bank grps)
    // B: [k][n] (n contiguous), rows padded to 136 bf16 (272B: same property)
    __shared__ __align__(16) __nv_bfloat16 As_hi[128][40];
    __shared__ __align__(16) __nv_bfloat16 As_lo[128][40];
    __shared__ __align__(16) __nv_bfloat16 Bs_hi[32][136];
    __shared__ __align__(16) __nv_bfloat16 Bs_lo[32][136];

    const int tid = threadIdx.x;
    const int warp = tid >> 5, lane = tid & 31;
    const int row0 = blockIdx.x * 128;
    const int col0 = blockIdx.y * 128;

    // staging: A thread covers row=tid>>1, k window (tid&1)*16 .. +15
    const int sar = tid >> 1, sak = (tid & 1) * 16;
    // B thread covers k=tid>>3, n window (tid&7)*16 .. +15
    const int sbk = tid >> 3, sbn = (tid & 7) * 16;
    const float* Ap = A + (size_t)(row0 + sar) * lda + sak;
    const float* Wp = W + (size_t)sbk * ldw + col0 + sbn;

    // ldmatrix lane geometry (shared by A and B x4 loads)
    const int warpM = (warp >> 2) * 64;
    const int warpN = (warp & 3) * 32;
    const int qr = (lane & 7) + ((lane >> 3) & 1) * 8;  // row within 16
    const int qc = (lane >> 4) * 8;                      // col half select
    uint32_t aHi = (uint32_t)__cvta_generic_to_shared(&As_hi[warpM + qr][qc]);
    uint32_t aLo = (uint32_t)__cvta_generic_to_shared(&As_lo[warpM + qr][qc]);
    uint32_t bHi = (uint32_t)__cvta_generic_to_shared(&Bs_hi[qr][warpN + qc]);
    uint32_t bLo = (uint32_t)__cvta_generic_to_shared(&Bs_lo[qr][warpN + qc]);
    const uint32_t ArowB = 40 * 2;    // bytes per As row
    const uint32_t BrowB = 136 * 2;   // bytes per Bs row

    float acc[4][4][4] = {};          // [mtile][ntile][frag]

    // prologue: prefetch first slab
    float4 pa[4], pb[4];
#pragma unroll
    for (int q = 0; q < 4; q++) {
        pa[q] = *(const float4*)(Ap + q * 4);
        pb[q] = *(const float4*)(Wp + q * 4);
    }

    for (int k0 = 0; k0 < 256; k0 += 32) {
        // stage current slab with hi/lo conversion
#pragma unroll
        for (int q = 0; q < 4; q++) {
            store_hilo(&As_hi[sar][sak + q * 4], &As_lo[sar][sak + q * 4], pa[q]);
            store_hilo(&Bs_hi[sbk][sbn + q * 4], &Bs_lo[sbk][sbn + q * 4], pb[q]);
        }
        __syncthreads();

        if (k0 + 32 < 256) {    // prefetch next slab (overlaps MMA phase)
#pragma unroll
            for (int q = 0; q < 4; q++) {
                pa[q] = *(const float4*)(Ap + k0 + 32 + q * 4);
                pb[q] = *(const float4*)(Wp + (size_t)(k0 + 32) * ldw + q * 4);
            }
        }

#pragma unroll
        for (int ks = 0; ks < 2; ks++) {
            uint32_t ah[4][4], al[4][4];
#pragma unroll
            for (int i = 0; i < 4; i++) {
                uint32_t off = (uint32_t)(i * 16) * ArowB + ks * 32;
                ldsm_x4(aHi + off, ah[i][0], ah[i][1], ah[i][2], ah[i][3]);
                ldsm_x4(aLo + off, al[i][0], al[i][1], al[i][2], al[i][3]);
            }
            uint32_t bh[2][4], bl[2][4];
#pragma unroll
            for (int j2 = 0; j2 < 2; j2++) {
                uint32_t off = (uint32_t)(j2 * 16) * 2 + ks * 16 * BrowB;
                ldsm_x4_t(bHi + off, bh[j2][0], bh[j2][1], bh[j2][2], bh[j2][3]);
                ldsm_x4_t(bLo + off, bl[j2][0], bl[j2][1], bl[j2][2], bl[j2][3]);
            }
            // 3 split terms, each a 4x4 sweep (dep distance 16 between same-acc MMAs)
#pragma unroll
            for (int i = 0; i < 4; i++)
#pragma unroll
                for (int j = 0; j < 4; j++)
                    mma16816(acc[i][j], ah[i], bh[j >> 1][(j & 1) * 2], bh[j >> 1][(j & 1) * 2 + 1]);
#pragma unroll
            for (int i = 0; i < 4; i++)
#pragma unroll
                for (int j = 0; j < 4; j++)
                    mma16816(acc[i][j], ah[i], bl[j >> 1][(j & 1) * 2], bl[j >> 1][(j & 1) * 2 + 1]);
#pragma unroll
            for (int i = 0; i < 4; i++)
#pragma unroll
                for (int j = 0; j < 4; j++)
                    mma16816(acc[i][j], al[i], bh[j >> 1][(j & 1) * 2], bh[j >> 1][(j & 1) * 2 + 1]);
        }
        __syncthreads();
    }

    // epilogue: c-frag layout: (er, ec)=(lane>>2, (lane&3)*2)
    const int er = lane >> 2, ec = (lane & 3) * 2;
#pragma unroll
    for (int i = 0; i < 4; i++) {
        int r0 = row0 + warpM + i * 16 + er;
#pragma unroll
        for (int j = 0; j < 4; j++) {
            int c = col0 + warpN + j * 8 + ec;
#pragma unroll
            for (int h = 0; h < 2; h++) {
                int row = r0 + h * 8;
                float v0 = acc[i][j][h * 2], v1 = acc[i][j][h * 2 + 1];
                float2 r;
                if (EPI == 0) {
                    r.x = fsilu(v0);
                    r.y = fsilu(v1);
                } else {
                    float2 vv = *(const float2*)(A + (size_t)row * lda + c);
                    float2 oo = *(const float2*)(outn + (size_t)row * CDIM + c);
                    float2 bb = *(const float2*)(bias + c);
                    float g;
                    g = fsig(fsilu(v0 + bb.x)); r.x = g * vv.x + (1.f - g) * oo.x;
                    g = fsig(fsilu(v1 + bb.y)); r.y = g * vv.y + (1.f - g) * oo.y;
                }
                *(float2*)(Cout + (size_t)row * ldc + c) = r;
            }
        }
    }
}

// ---------------------------------------------------------------------------
// wp = silu(x @ W_wp + b_wp); width = sig(.)*maxd+0.5, sharp = sig(.)*9.5+0.5
// ---------------------------------------------------------------------------
__global__ void __launch_bounds__(256) wp_kernel(
    const float* __restrict__ x, const float* __restrict__ W_wp,
    const float* __restrict__ b_wp, float* __restrict__ wp_out)
{
    int warp = (blockIdx.x * blockDim.x + threadIdx.x) >> 5;
    int lane = threadIdx.x & 31;
    if (warp >= NTOK) return;
    const float* xr = x + (size_t)warp * CDIM;
    float acc[8] = {};
    for (int k = lane; k < CDIM; k += 32) {
        float xv = xr[k];
        const float* wr = W_wp + k * 8;
#pragma unroll
        for (int o = 0; o < 8; o++) acc[o] += xv * wr[o];
    }
#pragma unroll
    for (int o = 0; o < 8; o++)
#pragma unroll
        for (int off = 16; off; off >>= 1)
            acc[o] += __shfl_xor_sync(0xffffffffu, acc[o], off);
    if (lane < 8) {
        const float maxd = 4.242640687119285f;  // sqrt(18)
        float t = acc[lane] + b_wp[lane];
        float s = fsilu(t);
        float sg = fsig(s);
        wp_out[warp * 8 + lane] = (lane < 4) ? (sg * maxd + 0.5f) : (sg * 9.5f + 0.5f);
    }
}

// ---------------------------------------------------------------------------
// In-place rmsnorm (per head, D=64) + RoPE (position = head index) on q, k.
// ---------------------------------------------------------------------------
__global__ void __launch_bounds__(256) rmsrope_kernel(
    const float* __restrict__ w_qnorm, const float* __restrict__ w_knorm)
{
    int token = blockIdx.x;
    int warpId = threadIdx.x >> 5, lane = threadIdx.x & 31;
    int which = warpId >> 2;    // 0=q, 1=k
    int head  = warpId & 3;
    const float* wn = which ? w_knorm : w_qnorm;
    float* base = g_qkv + (size_t)token * QKVN + which * CDIM + head * 64;

    float x1 = base[lane], x2 = base[lane + 32];
    float ss = x1 * x1 + x2 * x2;
#pragma unroll
    for (int off = 16; off; off >>= 1) ss += __shfl_xor_sync(0xffffffffu, ss, off);
    float inv = rsqrtf(ss * (1.f / 64.f) + 1e-6f);
    x1 = x1 * inv * wn[lane];
    x2 = x2 * inv * wn[lane + 32];

    float freq = exp2f(-(float)lane * (13.287712379549449f / 32.f));  // log2(10000)/32
    float ang = (float)head * freq;
    float c = cosf(ang), s = sinf(ang);
    base[lane]      = x1 * c - x2 * s;
    base[lane + 32] = x1 * s + x2 * c;
}

// ---------------------------------------------------------------------------
// Attention: 1 warp per (token, head), 2 tokens per 256-thread block.
// Phase 1: 4 groups of 8 lanes; group = window, lane = 8 channels (coalesced).
// Phase 2: warp softmax (scores via smem).
// Phase 3: lane = channel, coalesced v gathers. Fused per-token rmsnorm.
// ---------------------------------------------------------------------------
__global__ void __launch_bounds__(256) attn_kernel(const float* __restrict__ w_onorm)
{
    __shared__ __align__(16) float s_q[8][64];
    __shared__ float s_p[8][52];
    __shared__ float s_out[2][256];
    __shared__ float s_ss[2];

    const int warpId = threadIdx.x >> 5, lane = threadIdx.x & 31;
    const int tl = warpId >> 2;      // token-local 0/1
    const int head = warpId & 3;
    const int token = blockIdx.x * 2 + tl;
    const int b = token >> 12;
    const int yx = token & 4095;
    const int y = yx >> 6, xx = yx & 63;

    if (threadIdx.x < 2) s_ss[threadIdx.x] = 0.f;

    const float* qrow = g_qkv + (size_t)token * QKVN + head * 64;
    s_q[warpId][lane]      = qrow[lane];
    s_q[warpId][lane + 32] = qrow[lane + 32];
    __syncwarp();

    const int sub = lane & 7;        // lane within group
    const int grp = lane >> 3;       // group = window within round
    float4 q4a = ((const float4*)s_q[warpId])[sub];
    float4 q4b = ((const float4*)s_q[warpId])[sub + 8];

    const float width = g_wp[token * 8 + head];
    const float sharp = g_wp[token * 8 + 4 + head];
    const float* kbase = g_qkv + 256 + (size_t)head * 64;

#pragma unroll
    for (int r = 0; r < 13; r++) {
        int w = r * 4 + grp;
        bool act = (w < 49);
        int wc = act ? w : 48;
        int di = wc / 7 - 3, dj = wc % 7 - 3;
        int ny = y + di, nx = xx + dj;
        float part = 0.f;
        if (act & ((unsigned)ny < 64u) & ((unsigned)nx < 64u)) {
            const float4* kr = (const float4*)(kbase +
                (size_t)((b << 12) + (ny << 6) + nx) * QKVN);
            float4 ka = kr[sub];
            float4 kb = kr[sub + 8];
            part = q4a.x * ka.x + q4a.y * ka.y + q4a.z * ka.z + q4a.w * ka.w
                 + q4b.x * kb.x + q4b.y * kb.y + q4b.z * kb.z + q4b.w * kb.w;
        }
        part += __shfl_xor_sync(0xffffffffu, part, 1);
        part += __shfl_xor_sync(0xffffffffu, part, 2);
        part += __shfl_xor_sync(0xffffffffu, part, 4);
        if (act && sub == 0) {
            float rd = sqrtf((float)(di * di + dj * dj));
            float mask = fsig((width - rd) * sharp);
            s_p[warpId][w] = part * 0.125f - (1.f - mask) * 10000.f;
        }
    }
    __syncwarp();

    float sc0 = s_p[warpId][lane];
    float sc1 = (lane + 32 < 49) ? s_p[warpId][lane + 32] : -1e30f;
    float mx = fmaxf(sc0, sc1);
#pragma unroll
    for (int off = 16; off; off >>= 1) mx = fmaxf(mx, __shfl_xor_sync(0xffffffffu, mx, off));
    float p0 = __expf(sc0 - mx);
    float p1 = __expf(sc1 - mx);
    float ds = p0 + p1;
#pragma unroll
    for (int off = 16; off; off >>= 1) ds += __shfl_xor_sync(0xffffffffu, ds, off);
    float rdm = 1.f / ds;
    s_p[warpId][lane] = p0 * rdm;
    if (lane + 32 < 49) s_p[warpId][lane + 32] = p1 * rdm;
    __syncwarp();

    float o0 = 0.f, o1 = 0.f;
#pragma unroll
    for (int ii = 0; ii < 7; ii++) {
        int ny = y + ii - 3;
        if ((unsigned)ny >= 64u) continue;
        const float* rowbase = g_qkv + (size_t)((b << 12) + (ny << 6)) * QKVN
                             + 512 + head * 64;
#pragma unroll
        for (int jj = 0; jj < 7; jj++) {
            int nx = xx + jj - 3;
            if ((unsigned)nx >= 64u) continue;
            float p = s_p[warpId][ii * 7 + jj];
            const float* vrow = rowbase + (size_t)nx * QKVN;
            o0 += p * vrow[lane];
            o1 += p * vrow[lane + 32];
        }
    }

    s_out[tl][head * 64 + lane]      = o0;
    s_out[tl][head * 64 + lane + 32] = o1;

    float pss = o0 * o0 + o1 * o1;
#pragma unroll
    for (int off = 16; off; off >>= 1) pss += __shfl_xor_sync(0xffffffffu, pss, off);
    __syncthreads();            // s_ss init + s_out visible
    if (lane == 0) atomicAdd(&s_ss[tl], pss);
    __syncthreads();

    for (int e = threadIdx.x; e < 512; e += 256) {
        int t2 = e >> 8, c = e & 255;
        float rinv = rsqrtf(s_ss[t2] * (1.f / 256.f) + 1e-6f);
        g_outn[(size_t)(blockIdx.x * 2 + t2) * CDIM + c] = s_out[t2][c] * rinv * w_onorm[c];
    }
}

// ---------------------------------------------------------------------------
extern "C" void kernel_launch(void* const* d_in, const int* in_sizes, int n_in,
                              void* d_out, int out_size)
{
    const float* x       = (const float*)d_in[0];
    const float* W_qkv   = (const float*)d_in[1];
    const float* w_qnorm = (const float*)d_in[2];
    const float* w_knorm = (const float*)d_in[3];
    const float* W_wp    = (const float*)d_in[4];
    const float* b_wp    = (const float*)d_in[5];
    const float* w_onorm = (const float*)d_in[6];
    const float* W_out   = (const float*)d_in[7];
    const float* W_gate  = (const float*)d_in[8];
    const float* b_gate  = (const float*)d_in[9];
    float* out = (float*)d_out;

    float *p_qkv, *p_wp, *p_outn, *p_merged;
    cudaGetSymbolAddress((void**)&p_qkv, g_qkv);
    cudaGetSymbolAddress((void**)&p_wp, g_wp);
    cudaGetSymbolAddress((void**)&p_outn, g_outn);
    cudaGetSymbolAddress((void**)&p_merged, g_merged);

    // 1. qkv = silu(x @ W_qkv)
    gemm_bf16s<0><<<dim3(NTOK / 128, QKVN / 128), 256>>>(x, CDIM, W_qkv, QKVN, nullptr,
                                                         p_qkv, QKVN, nullptr);
    // 2. width/sharpness projection
    wp_kernel<<<NTOK / 8, 256>>>(x, W_wp, b_wp, p_wp);
    // 3. rmsnorm + rope on q, k (in place)
    rmsrope_kernel<<<NTOK, 256>>>(w_qnorm, w_knorm);
    // 4. windowed attention + fused output rmsnorm
    attn_kernel<<<NTOK / 2, 256>>>(w_onorm);
    // 5. gate GEMM + merge epilogue: merged = gate*v + (1-gate)*outn
    gemm_bf16s<1><<<dim3(NTOK / 128, CDIM / 128), 256>>>(p_qkv + 512, QKVN, W_gate, CDIM,
                                                         b_gate, p_merged, CDIM, p_outn);
    // 6. final: silu(merged @ W_out)
    gemm_bf16s<0><<<dim3(NTOK / 128, CDIM / 128), 256>>>(p_merged, CDIM, W_out, CDIM, nullptr,
                                                         out, CDIM, nullptr);
}